// round 1
// baseline (speedup 1.0000x reference)
#include <cuda_runtime.h>
#include <math.h>

#define THREADS 256

// ---- shared memory layout (float offsets) ----
#define XBUF_OFF 0            // [64][256] activations
#define EMB_OFF  16384        // [64][64]  xyz harmonic emb (later reused cols 0..31 for dir emb)
#define WS_OFF   20480        // [256][34] transposed weight chunk (pad 34 -> conflict-free LDS.64)
#define DENS_OFF 29184        // [64] density
#define EMBD_OFF 29248        // [32] per-ray dir emb scratch
#define SMEM_FLOATS 29280
#define SMEM_BYTES (SMEM_FLOATS * 4)

// Blackwell packed fp32 FMA: d.{lo,hi} += a.{lo,hi} * b.{lo,hi}
__device__ __forceinline__ void fma2(unsigned long long& d, unsigned long long a, unsigned long long b) {
    asm("fma.rn.f32x2 %0, %1, %2, %0;" : "+l"(d) : "l"(a), "l"(b));
}

// One fused layer: xbuf[64][OUT] = relu(A * W^T + b), A drawn from xbuf chunks then emb chunks.
// W is [OUT][in_act] row-major in global. OUT = NJ*32. Each thread computes 8m x NJ outputs
// (m = warp*8 + i, o = lane + 32*j). k processed in pairs; accumulator halves hold
// even-k / odd-k partial sums, folded at writeback.
template<int NJ>
__device__ __forceinline__ void gemm_layer(
    const float* __restrict__ Wg, const float* __restrict__ bg,
    int in_act, int nchunks, int xchunks,
    float* xbuf, float* emb, float* wsT)
{
    const int tid  = threadIdx.x;
    const int lane = tid & 31;
    const int mb   = (tid >> 5) << 3;

    unsigned long long acc[8][NJ];
#pragma unroll
    for (int i = 0; i < 8; ++i)
#pragma unroll
        for (int j = 0; j < NJ; ++j) acc[i][j] = 0ull;

    for (int c = 0; c < nchunks; ++c) {
        __syncthreads();                       // prev chunk fully consumed / prev writeback done
        const int k0 = c << 5;
        // stage W chunk transposed: wsT[o][kk] = W[o][k0+kk] (zero-pad past in_act)
        for (int idx = tid; idx < NJ * 32 * 32; idx += THREADS) {
            int kk = idx & 31;
            int o  = idx >> 5;
            int k  = k0 + kk;
            wsT[o * 34 + kk] = (k < in_act) ? __ldg(Wg + o * in_act + k) : 0.0f;
        }
        const float* As;
        int lda;
        if (c < xchunks) { As = xbuf + k0;                    lda = 256; }
        else             { As = emb + ((c - xchunks) << 5);   lda = 64;  }
        __syncthreads();
#pragma unroll 1
        for (int kk2 = 0; kk2 < 16; ++kk2) {   // 16 k-pairs per 32-wide chunk
            unsigned long long a[8];
#pragma unroll
            for (int i = 0; i < 8; ++i)        // warp-uniform address -> LDS broadcast
                a[i] = *reinterpret_cast<const unsigned long long*>(As + (mb + i) * lda + (kk2 << 1));
#pragma unroll
            for (int j = 0; j < NJ; ++j) {
                unsigned long long w = *reinterpret_cast<const unsigned long long*>(
                    wsT + (lane + (j << 5)) * 34 + (kk2 << 1));
#pragma unroll
                for (int i = 0; i < 8; ++i) fma2(acc[i][j], a[i], w);
            }
        }
    }
    __syncthreads();   // all reads of xbuf done before overwrite
#pragma unroll
    for (int j = 0; j < NJ; ++j) {
        const int o = lane + (j << 5);
        const float bias = __ldg(bg + o);
#pragma unroll
        for (int i = 0; i < 8; ++i) {
            float lo = __uint_as_float((unsigned)(acc[i][j] & 0xffffffffull));
            float hi = __uint_as_float((unsigned)(acc[i][j] >> 32));
            float r  = fmaxf(lo + hi + bias, 0.0f);
            xbuf[(mb + i) * 256 + o] = r;
        }
    }
    __syncthreads();
}

__global__ void __launch_bounds__(THREADS, 1) nerf_fused(
    const float* __restrict__ sp,   const float* __restrict__ dirs,
    const float* __restrict__ Wx0,  const float* __restrict__ bx0,
    const float* __restrict__ Wx1,  const float* __restrict__ bx1,
    const float* __restrict__ Wx2,  const float* __restrict__ bx2,
    const float* __restrict__ Wx3,  const float* __restrict__ bx3,
    const float* __restrict__ Wx4,  const float* __restrict__ bx4,
    const float* __restrict__ Wx5,  const float* __restrict__ bx5,
    const float* __restrict__ Wx6,  const float* __restrict__ bx6,
    const float* __restrict__ Wx7,  const float* __restrict__ bx7,
    const float* __restrict__ Wd0,  const float* __restrict__ bd0,
    const float* __restrict__ Wden, const float* __restrict__ bden,
    const float* __restrict__ Wfeat,const float* __restrict__ bfeat,
    const float* __restrict__ Wrgb, const float* __restrict__ brgb,
    float* __restrict__ out)
{
    extern __shared__ float sm[];
    float* xbuf = sm + XBUF_OFF;
    float* emb  = sm + EMB_OFF;
    float* wsT  = sm + WS_OFF;
    float* dens = sm + DENS_OFF;
    float* embd = sm + EMBD_OFF;

    const int tid  = threadIdx.x;
    const int lane = tid & 31;
    const int warp = tid >> 5;
    const int p0   = blockIdx.x << 6;   // 64 samples = exactly one ray per block

    // ---- Phase 0: xyz harmonic embedding: [sin(30), cos(30), xyz(3), pad0] ----
    if (tid < 64) {
        const float* pp = sp + (size_t)(p0 + tid) * 3;
        float* e = emb + tid * 64;
#pragma unroll
        for (int d = 0; d < 3; ++d) {
            float x = pp[d];
            float f = 1.0f;
#pragma unroll
            for (int h = 0; h < 10; ++h) {
                float s, c;
                sincosf(x * f, &s, &c);
                e[d * 10 + h]      = s;
                e[30 + d * 10 + h] = c;
                f *= 2.0f;
            }
            e[60 + d] = x;
        }
        e[63] = 0.0f;
    }
    // gemm_layer's leading __syncthreads orders phase 0 vs first reads

    gemm_layer<8>(Wx0, bx0,  63,  2, 0, xbuf, emb, wsT);   // 63->256 (from emb)
    gemm_layer<8>(Wx1, bx1, 256,  8, 8, xbuf, emb, wsT);
    gemm_layer<8>(Wx2, bx2, 256,  8, 8, xbuf, emb, wsT);
    gemm_layer<8>(Wx3, bx3, 256,  8, 8, xbuf, emb, wsT);
    gemm_layer<8>(Wx4, bx4, 319, 10, 8, xbuf, emb, wsT);   // skip: [h(256), emb_x(63)]
    gemm_layer<8>(Wx5, bx5, 256,  8, 8, xbuf, emb, wsT);
    gemm_layer<8>(Wx6, bx6, 256,  8, 8, xbuf, emb, wsT);
    gemm_layer<8>(Wx7, bx7, 256,  8, 8, xbuf, emb, wsT);

    // ---- density head (reads xbuf before feat overwrites it) ----
    {
        const float bd = __ldg(bden);
#pragma unroll 1
        for (int it = 0; it < 8; ++it) {
            int m = warp + (it << 3);
            float s = 0.0f;
#pragma unroll
            for (int kk = 0; kk < 8; ++kk) {
                int k = lane + (kk << 5);
                s += xbuf[m * 256 + k] * __ldg(Wden + k);
            }
#pragma unroll
            for (int off = 16; off > 0; off >>= 1) s += __shfl_xor_sync(0xffffffffu, s, off);
            if (lane == 0) dens[m] = fmaxf(s + bd, 0.0f);
        }
    }
    __syncthreads();

    gemm_layer<8>(Wfeat, bfeat, 256, 8, 8, xbuf, emb, wsT);

    // ---- direction embedding [sin(12), cos(12), dir(3), pad0] broadcast to emb[:, 0..31] ----
    if (tid < 32) {
        float v = 0.0f;
        if (tid < 12) {
            float x = __ldg(dirs + blockIdx.x * 3 + (tid >> 2));
            v = sinf(x * (float)(1 << (tid & 3)));
        } else if (tid < 24) {
            int kk = tid - 12;
            float x = __ldg(dirs + blockIdx.x * 3 + (kk >> 2));
            v = cosf(x * (float)(1 << (kk & 3)));
        } else if (tid < 27) {
            v = __ldg(dirs + blockIdx.x * 3 + (tid - 24));
        }
        embd[tid] = v;
    }
    __syncthreads();
    for (int idx = tid; idx < 64 * 32; idx += THREADS)
        emb[(idx >> 5) * 64 + (idx & 31)] = embd[idx & 31];

    gemm_layer<4>(Wd0, bd0, 283, 9, 8, xbuf, emb, wsT);    // [feat(256), emb_d(27)] -> 128

    // ---- rgb head + output ----
    {
#pragma unroll 1
        for (int it = 0; it < 8; ++it) {
            int m = warp + (it << 3);
            float s0 = 0.0f, s1 = 0.0f, s2 = 0.0f;
#pragma unroll
            for (int kk = 0; kk < 4; ++kk) {
                int k = lane + (kk << 5);
                float h = xbuf[m * 256 + k];
                s0 += h * __ldg(Wrgb + k);
                s1 += h * __ldg(Wrgb + 128 + k);
                s2 += h * __ldg(Wrgb + 256 + k);
            }
#pragma unroll
            for (int off = 16; off > 0; off >>= 1) {
                s0 += __shfl_xor_sync(0xffffffffu, s0, off);
                s1 += __shfl_xor_sync(0xffffffffu, s1, off);
                s2 += __shfl_xor_sync(0xffffffffu, s2, off);
            }
            if (lane == 0) {
                float* op = out + (size_t)(p0 + m) * 4;
                op[0] = dens[m];
                op[1] = 1.0f / (1.0f + expf(-(s0 + __ldg(brgb))));
                op[2] = 1.0f / (1.0f + expf(-(s1 + __ldg(brgb + 1))));
                op[3] = 1.0f / (1.0f + expf(-(s2 + __ldg(brgb + 2))));
            }
        }
    }
}

extern "C" void kernel_launch(void* const* d_in, const int* in_sizes, int n_in,
                              void* d_out, int out_size) {
    (void)in_sizes; (void)n_in; (void)out_size;
    cudaFuncSetAttribute(nerf_fused, cudaFuncAttributeMaxDynamicSharedMemorySize, SMEM_BYTES);
    nerf_fused<<<4096, THREADS, SMEM_BYTES>>>(
        (const float*)d_in[0],  (const float*)d_in[1],
        (const float*)d_in[2],  (const float*)d_in[3],
        (const float*)d_in[4],  (const float*)d_in[5],
        (const float*)d_in[6],  (const float*)d_in[7],
        (const float*)d_in[8],  (const float*)d_in[9],
        (const float*)d_in[10], (const float*)d_in[11],
        (const float*)d_in[12], (const float*)d_in[13],
        (const float*)d_in[14], (const float*)d_in[15],
        (const float*)d_in[16], (const float*)d_in[17],
        (const float*)d_in[18], (const float*)d_in[19],
        (const float*)d_in[20], (const float*)d_in[21],
        (const float*)d_in[22], (const float*)d_in[23],
        (const float*)d_in[24], (const float*)d_in[25],
        (float*)d_out);
}

// round 2
// speedup vs baseline: 1.0008x; 1.0008x over previous
#include <cuda_runtime.h>
#include <math.h>

#define THREADS 256

// ---- shared memory layout (float offsets) ----
#define XBUF_OFF 0            // [64][256] activations
#define EMB_OFF  16384        // [64][64]  xyz harmonic emb (later reused cols 0..31 for dir emb)
#define WS_OFF   20480        // [256][34] transposed weight chunk (pad 34 -> conflict-free LDS.64)
#define DENS_OFF 29184        // [64] density
#define EMBD_OFF 29248        // [32] per-ray dir emb scratch
#define SMEM_FLOATS 29280
#define SMEM_BYTES (SMEM_FLOATS * 4)

// Blackwell packed fp32 FMA: d.{lo,hi} += a.{lo,hi} * b.{lo,hi}
__device__ __forceinline__ void fma2(unsigned long long& d, unsigned long long a, unsigned long long b) {
    asm("fma.rn.f32x2 %0, %1, %2, %0;" : "+l"(d) : "l"(a), "l"(b));
}

// One fused layer: xbuf[64][OUT] = relu(A * W^T + b), A drawn from xbuf chunks then emb chunks.
// W is [OUT][in_act] row-major in global. OUT = NJ*32. Each thread computes 8m x NJ outputs
// (m = warp*8 + i, o = lane + 32*j). k processed in pairs; accumulator halves hold
// even-k / odd-k partial sums, folded at writeback.
template<int NJ>
__device__ __forceinline__ void gemm_layer(
    const float* __restrict__ Wg, const float* __restrict__ bg,
    int in_act, int nchunks, int xchunks,
    float* xbuf, float* emb, float* wsT)
{
    const int tid  = threadIdx.x;
    const int lane = tid & 31;
    const int mb   = (tid >> 5) << 3;

    unsigned long long acc[8][NJ];
#pragma unroll
    for (int i = 0; i < 8; ++i)
#pragma unroll
        for (int j = 0; j < NJ; ++j) acc[i][j] = 0ull;

    for (int c = 0; c < nchunks; ++c) {
        __syncthreads();                       // prev chunk fully consumed / prev writeback done
        const int k0 = c << 5;
        // stage W chunk transposed: wsT[o][kk] = W[o][k0+kk] (zero-pad past in_act)
        for (int idx = tid; idx < NJ * 32 * 32; idx += THREADS) {
            int kk = idx & 31;
            int o  = idx >> 5;
            int k  = k0 + kk;
            wsT[o * 34 + kk] = (k < in_act) ? __ldg(Wg + o * in_act + k) : 0.0f;
        }
        const float* As;
        int lda;
        if (c < xchunks) { As = xbuf + k0;                    lda = 256; }
        else             { As = emb + ((c - xchunks) << 5);   lda = 64;  }
        __syncthreads();
#pragma unroll 1
        for (int kk2 = 0; kk2 < 16; ++kk2) {   // 16 k-pairs per 32-wide chunk
            unsigned long long a[8];
#pragma unroll
            for (int i = 0; i < 8; ++i)        // warp-uniform address -> LDS broadcast
                a[i] = *reinterpret_cast<const unsigned long long*>(As + (mb + i) * lda + (kk2 << 1));
#pragma unroll
            for (int j = 0; j < NJ; ++j) {
                unsigned long long w = *reinterpret_cast<const unsigned long long*>(
                    wsT + (lane + (j << 5)) * 34 + (kk2 << 1));
#pragma unroll
                for (int i = 0; i < 8; ++i) fma2(acc[i][j], a[i], w);
            }
        }
    }
    __syncthreads();   // all reads of xbuf done before overwrite
#pragma unroll
    for (int j = 0; j < NJ; ++j) {
        const int o = lane + (j << 5);
        const float bias = __ldg(bg + o);
#pragma unroll
        for (int i = 0; i < 8; ++i) {
            float lo = __uint_as_float((unsigned)(acc[i][j] & 0xffffffffull));
            float hi = __uint_as_float((unsigned)(acc[i][j] >> 32));
            float r  = fmaxf(lo + hi + bias, 0.0f);
            xbuf[(mb + i) * 256 + o] = r;
        }
    }
    __syncthreads();
}

__global__ void __launch_bounds__(THREADS, 1) nerf_fused(
    const float* __restrict__ sp,   const float* __restrict__ dirs,
    const float* __restrict__ Wx0,  const float* __restrict__ bx0,
    const float* __restrict__ Wx1,  const float* __restrict__ bx1,
    const float* __restrict__ Wx2,  const float* __restrict__ bx2,
    const float* __restrict__ Wx3,  const float* __restrict__ bx3,
    const float* __restrict__ Wx4,  const float* __restrict__ bx4,
    const float* __restrict__ Wx5,  const float* __restrict__ bx5,
    const float* __restrict__ Wx6,  const float* __restrict__ bx6,
    const float* __restrict__ Wx7,  const float* __restrict__ bx7,
    const float* __restrict__ Wd0,  const float* __restrict__ bd0,
    const float* __restrict__ Wden, const float* __restrict__ bden,
    const float* __restrict__ Wfeat,const float* __restrict__ bfeat,
    const float* __restrict__ Wrgb, const float* __restrict__ brgb,
    float* __restrict__ out)
{
    extern __shared__ float sm[];
    float* xbuf = sm + XBUF_OFF;
    float* emb  = sm + EMB_OFF;
    float* wsT  = sm + WS_OFF;
    float* dens = sm + DENS_OFF;
    float* embd = sm + EMBD_OFF;

    const int tid  = threadIdx.x;
    const int lane = tid & 31;
    const int warp = tid >> 5;
    const int p0   = blockIdx.x << 6;   // 64 samples = exactly one ray per block

    // ---- Phase 0: xyz harmonic embedding: [sin(30), cos(30), xyz(3), pad0] ----
    if (tid < 64) {
        const float* pp = sp + (size_t)(p0 + tid) * 3;
        float* e = emb + tid * 64;
#pragma unroll
        for (int d = 0; d < 3; ++d) {
            float x = pp[d];
            float f = 1.0f;
#pragma unroll
            for (int h = 0; h < 10; ++h) {
                float s, c;
                sincosf(x * f, &s, &c);
                e[d * 10 + h]      = s;
                e[30 + d * 10 + h] = c;
                f *= 2.0f;
            }
            e[60 + d] = x;
        }
        e[63] = 0.0f;
    }
    // gemm_layer's leading __syncthreads orders phase 0 vs first reads

    gemm_layer<8>(Wx0, bx0,  63,  2, 0, xbuf, emb, wsT);   // 63->256 (from emb)
    gemm_layer<8>(Wx1, bx1, 256,  8, 8, xbuf, emb, wsT);
    gemm_layer<8>(Wx2, bx2, 256,  8, 8, xbuf, emb, wsT);
    gemm_layer<8>(Wx3, bx3, 256,  8, 8, xbuf, emb, wsT);
    gemm_layer<8>(Wx4, bx4, 319, 10, 8, xbuf, emb, wsT);   // skip: [h(256), emb_x(63)]
    gemm_layer<8>(Wx5, bx5, 256,  8, 8, xbuf, emb, wsT);
    gemm_layer<8>(Wx6, bx6, 256,  8, 8, xbuf, emb, wsT);
    gemm_layer<8>(Wx7, bx7, 256,  8, 8, xbuf, emb, wsT);

    // ---- density head (reads xbuf before feat overwrites it) ----
    {
        const float bd = __ldg(bden);
#pragma unroll 1
        for (int it = 0; it < 8; ++it) {
            int m = warp + (it << 3);
            float s = 0.0f;
#pragma unroll
            for (int kk = 0; kk < 8; ++kk) {
                int k = lane + (kk << 5);
                s += xbuf[m * 256 + k] * __ldg(Wden + k);
            }
#pragma unroll
            for (int off = 16; off > 0; off >>= 1) s += __shfl_xor_sync(0xffffffffu, s, off);
            if (lane == 0) dens[m] = fmaxf(s + bd, 0.0f);
        }
    }
    __syncthreads();

    gemm_layer<8>(Wfeat, bfeat, 256, 8, 8, xbuf, emb, wsT);

    // ---- direction embedding [sin(12), cos(12), dir(3), pad0] broadcast to emb[:, 0..31] ----
    if (tid < 32) {
        float v = 0.0f;
        if (tid < 12) {
            float x = __ldg(dirs + blockIdx.x * 3 + (tid >> 2));
            v = sinf(x * (float)(1 << (tid & 3)));
        } else if (tid < 24) {
            int kk = tid - 12;
            float x = __ldg(dirs + blockIdx.x * 3 + (kk >> 2));
            v = cosf(x * (float)(1 << (kk & 3)));
        } else if (tid < 27) {
            v = __ldg(dirs + blockIdx.x * 3 + (tid - 24));
        }
        embd[tid] = v;
    }
    __syncthreads();
    for (int idx = tid; idx < 64 * 32; idx += THREADS)
        emb[(idx >> 5) * 64 + (idx & 31)] = embd[idx & 31];

    gemm_layer<4>(Wd0, bd0, 283, 9, 8, xbuf, emb, wsT);    // [feat(256), emb_d(27)] -> 128

    // ---- rgb head + output ----
    {
#pragma unroll 1
        for (int it = 0; it < 8; ++it) {
            int m = warp + (it << 3);
            float s0 = 0.0f, s1 = 0.0f, s2 = 0.0f;
#pragma unroll
            for (int kk = 0; kk < 4; ++kk) {
                int k = lane + (kk << 5);
                float h = xbuf[m * 256 + k];
                s0 += h * __ldg(Wrgb + k);
                s1 += h * __ldg(Wrgb + 128 + k);
                s2 += h * __ldg(Wrgb + 256 + k);
            }
#pragma unroll
            for (int off = 16; off > 0; off >>= 1) {
                s0 += __shfl_xor_sync(0xffffffffu, s0, off);
                s1 += __shfl_xor_sync(0xffffffffu, s1, off);
                s2 += __shfl_xor_sync(0xffffffffu, s2, off);
            }
            if (lane == 0) {
                float* op = out + (size_t)(p0 + m) * 4;
                op[0] = dens[m];
                op[1] = 1.0f / (1.0f + expf(-(s0 + __ldg(brgb))));
                op[2] = 1.0f / (1.0f + expf(-(s1 + __ldg(brgb + 1))));
                op[3] = 1.0f / (1.0f + expf(-(s2 + __ldg(brgb + 2))));
            }
        }
    }
}

extern "C" void kernel_launch(void* const* d_in, const int* in_sizes, int n_in,
                              void* d_out, int out_size) {
    (void)in_sizes; (void)n_in; (void)out_size;
    cudaFuncSetAttribute(nerf_fused, cudaFuncAttributeMaxDynamicSharedMemorySize, SMEM_BYTES);
    nerf_fused<<<4096, THREADS, SMEM_BYTES>>>(
        (const float*)d_in[0],  (const float*)d_in[1],
        (const float*)d_in[2],  (const float*)d_in[3],
        (const float*)d_in[4],  (const float*)d_in[5],
        (const float*)d_in[6],  (const float*)d_in[7],
        (const float*)d_in[8],  (const float*)d_in[9],
        (const float*)d_in[10], (const float*)d_in[11],
        (const float*)d_in[12], (const float*)d_in[13],
        (const float*)d_in[14], (const float*)d_in[15],
        (const float*)d_in[16], (const float*)d_in[17],
        (const float*)d_in[18], (const float*)d_in[19],
        (const float*)d_in[20], (const float*)d_in[21],
        (const float*)d_in[22], (const float*)d_in[23],
        (const float*)d_in[24], (const float*)d_in[25],
        (float*)d_out);
}